// round 14
// baseline (speedup 1.0000x reference)
#include <cuda_runtime.h>
#include <cuda_fp16.h>
#include <math.h>

#define NMAX 100000
#define EMAX 1700000
#define DIM1 128
#define HID  64

// ---------------- device scratch ----------------
__device__ __align__(16) __half g_h1[NMAX * HID];   // fp16 features (layer1)
__device__ __align__(16) __half g_h2[NMAX * HID];   // fp16 features (layer2)
__device__ __align__(16) float g_as1n[NMAX * 8];
__device__ __align__(16) float g_ad1n[NMAX * 8];
__device__ __align__(16) float g_hx  [NMAX * HID];
__device__ __align__(16) float g_as2n[NMAX];
__device__ __align__(16) float g_ad2n[NMAX];
__device__ __align__(16) float g_z   [NMAX * HID];
// CSR
__device__ int g_cnt   [NMAX];
__device__ int g_rowptr[NMAX + 1];
__device__ int g_col   [EMAX];
__device__ int g_sums  [128];

// ---------------- helpers ----------------
__device__ __forceinline__ int clampi(int i, int N) {
    i = i < 0 ? 0 : i;
    return i >= N ? N - 1 : i;
}
__device__ __forceinline__ float lrelu(float v) { return v > 0.0f ? v : 0.2f * v; }
__device__ __forceinline__ float f4elem(float4 v, int kk) {
    return kk == 0 ? v.x : kk == 1 ? v.y : kk == 2 ? v.z : v.w;
}

typedef unsigned long long ull;
__device__ __forceinline__ ull pack2(float lo, float hi) {
    ull r; asm("mov.b64 %0,{%1,%2};" : "=l"(r) : "f"(lo), "f"(hi)); return r;
}
__device__ __forceinline__ void unpack2(ull v, float& lo, float& hi) {
    asm("mov.b64 {%0,%1},%2;" : "=f"(lo), "=f"(hi) : "l"(v));
}
__device__ __forceinline__ ull fma2(ull a, ull b, ull c) {
    ull d; asm("fma.rn.f32x2 %0,%1,%2,%3;" : "=l"(d) : "l"(a), "l"(b), "l"(c)); return d;
}
__device__ __forceinline__ uint2 to_h4(float a0, float a1, float a2, float a3) {
    __half2 p0 = __float22half2_rn(make_float2(a0, a1));
    __half2 p1 = __float22half2_rn(make_float2(a2, a3));
    uint2 u;
    u.x = *(unsigned*)&p0;
    u.y = *(unsigned*)&p1;
    return u;
}
// tensor-core primitives
__device__ __forceinline__ void ldsm_x4(unsigned& r0, unsigned& r1, unsigned& r2, unsigned& r3, unsigned a) {
    asm volatile("ldmatrix.sync.aligned.m8n8.x4.shared.b16 {%0,%1,%2,%3}, [%4];"
                 : "=r"(r0), "=r"(r1), "=r"(r2), "=r"(r3) : "r"(a));
}
__device__ __forceinline__ void ldsm_x4t(unsigned& r0, unsigned& r1, unsigned& r2, unsigned& r3, unsigned a) {
    asm volatile("ldmatrix.sync.aligned.m8n8.x4.trans.shared.b16 {%0,%1,%2,%3}, [%4];"
                 : "=r"(r0), "=r"(r1), "=r"(r2), "=r"(r3) : "r"(a));
}
__device__ __forceinline__ void mma16816(float* c, unsigned a0, unsigned a1, unsigned a2, unsigned a3,
                                         unsigned b0, unsigned b1) {
    asm volatile("mma.sync.aligned.m16n8k16.row.col.f32.f16.f16.f32 "
                 "{%0,%1,%2,%3}, {%4,%5,%6,%7}, {%8,%9}, {%0,%1,%2,%3};"
                 : "+f"(c[0]), "+f"(c[1]), "+f"(c[2]), "+f"(c[3])
                 : "r"(a0), "r"(a1), "r"(a2), "r"(a3), "r"(b0), "r"(b1));
}

// ================= CSR build =================
__global__ void count_kernel(const int* __restrict__ ei, int E, int N) {
    int i = blockIdx.x * blockDim.x + threadIdx.x;
    if (i < E) atomicAdd(&g_cnt[clampi(ei[(size_t)E + i], N)], 1);
}
__global__ __launch_bounds__(1024) void scan1_kernel(int N) {
    __shared__ int sh[1024];
    int i = blockIdx.x * 1024 + threadIdx.x;
    int v = (i < N) ? g_cnt[i] : 0;
    sh[threadIdx.x] = v; __syncthreads();
    #pragma unroll
    for (int o = 1; o < 1024; o <<= 1) {
        int t = 0;
        if (threadIdx.x >= o) t = sh[threadIdx.x - o];
        __syncthreads();
        if (threadIdx.x >= o) sh[threadIdx.x] += t;
        __syncthreads();
    }
    if (i < N) g_rowptr[i] = sh[threadIdx.x] - v;
    if (threadIdx.x == 1023) g_sums[blockIdx.x] = sh[1023];
}
// scan3 also performs the (<=128)-element scan of block sums
__global__ __launch_bounds__(256) void scan3_kernel(int N, int Etot, int nb) {
    __shared__ int ssum[128];
    __shared__ int sorig[128];
    int tid = threadIdx.x;
    if (tid < 128) {
        int v = (tid < nb) ? g_sums[tid] : 0;
        ssum[tid] = v; sorig[tid] = v;
    }
    __syncthreads();
    #pragma unroll
    for (int o = 1; o < 128; o <<= 1) {
        int tval = 0;
        if (tid < 128 && tid >= o) tval = ssum[tid - o];
        __syncthreads();
        if (tid < 128 && tid >= o) ssum[tid] += tval;
        __syncthreads();
    }
    int i = blockIdx.x * blockDim.x + tid;
    if (i < N) {
        int chunk = i >> 10;
        int rp = g_rowptr[i] + (ssum[chunk] - sorig[chunk]) + i;  // +i = self loops
        g_rowptr[i] = rp;
        g_col[rp] = i;          // self loop first in segment
        g_cnt[i] = rp + 1;      // scatter cursor
    }
    if (i == 0) g_rowptr[N] = Etot;
}
__global__ void scatter_kernel(const int* __restrict__ ei, int E, int N) {
    int i = blockIdx.x * blockDim.x + threadIdx.x;
    if (i >= E) return;
    int src = clampi(ei[i], N);
    int dst = clampi(ei[(size_t)E + i], N);
    int pos = atomicAdd(&g_cnt[dst], 1);
    g_col[pos] = src;
}

// ================= GEMM 1 (tensor cores): h1 = x @ W1 ; node alphas ==========
#define SA_PITCH 136
#define SB_PITCH 72
__global__ __launch_bounds__(256) void gemm1_kernel(
    const float* __restrict__ x, const float* __restrict__ W1,
    const float* __restrict__ as1, const float* __restrict__ ad1, int N)
{
    extern __shared__ __half smh[];
    __half* sA = smh;                     // 128 x 136 halves
    __half* sB = smh + 128 * SA_PITCH;    // 128 x 72 halves

    int t = threadIdx.x;
    int nodeBase = blockIdx.x * 128;
    int rows = min(128, N - nodeBase);

    for (int i = t; i < 128 * 16; i += 256) {
        int r = i >> 4, c4 = i & 15;
        float4 v = ((const float4*)W1)[i];
        *(uint2*)&sB[r * SB_PITCH + c4 * 4] = to_h4(v.x, v.y, v.z, v.w);
    }
    for (int i = t; i < 128 * 32; i += 256) {
        int r = i >> 5, c4 = i & 31;
        float4 v = make_float4(0.f, 0.f, 0.f, 0.f);
        if (r < rows) v = ((const float4*)(x + (size_t)nodeBase * DIM1))[i];
        *(uint2*)&sA[r * SA_PITCH + c4 * 4] = to_h4(v.x, v.y, v.z, v.w);
    }
    __syncthreads();

    int w = t >> 5, lane = t & 31;
    unsigned sAc = (unsigned)__cvta_generic_to_shared(sA);
    unsigned sBc = (unsigned)__cvta_generic_to_shared(sB);
    unsigned aBase = sAc + ((16 * w + (lane & 15)) * SA_PITCH + (lane >> 4) * 8) * 2;
    unsigned bLane = sBc + ((lane & 15) * SB_PITCH + (lane >> 4) * 8) * 2;

    float acc[8][4];
    #pragma unroll
    for (int nt = 0; nt < 8; nt++)
        #pragma unroll
        for (int m = 0; m < 4; m++) acc[nt][m] = 0.0f;

    #pragma unroll
    for (int s = 0; s < 8; s++) {
        unsigned a0, a1, a2, a3;
        ldsm_x4(a0, a1, a2, a3, aBase + s * 32);
        unsigned bStep = bLane + s * 16 * SB_PITCH * 2;
        #pragma unroll
        for (int nt = 0; nt < 8; nt += 2) {
            unsigned b0, b1, b2, b3;
            ldsm_x4t(b0, b1, b2, b3, bStep + nt * 16);
            mma16816(acc[nt],     a0, a1, a2, a3, b0, b1);
            mma16816(acc[nt + 1], a0, a1, a2, a3, b2, b3);
        }
    }

    int r_lo = 16 * w + (lane >> 2);
    int node_lo = nodeBase + r_lo;
    int node_hi = node_lo + 8;
    int c2i = (lane & 3) * 2;
    bool vlo = node_lo < N, vhi = node_hi < N;

    #pragma unroll
    for (int tile = 0; tile < 8; tile++) {
        int col = tile * 8 + c2i;
        float a0v = acc[tile][0], a1v = acc[tile][1];
        float a2v = acc[tile][2], a3v = acc[tile][3];
        if (vlo) {
            __half2 hv = __float22half2_rn(make_float2(a0v, a1v));
            *(__half2*)&g_h1[(size_t)node_lo * HID + col] = hv;
        }
        if (vhi) {
            __half2 hv = __float22half2_rn(make_float2(a2v, a3v));
            *(__half2*)&g_h1[(size_t)node_hi * HID + col] = hv;
        }
        float s0 = as1[col], s1v = as1[col + 1];
        float d0 = ad1[col], d1v = ad1[col + 1];
        float sl = a0v * s0 + a1v * s1v, dl = a0v * d0 + a1v * d1v;
        float sh = a2v * s0 + a3v * s1v, dh = a2v * d0 + a3v * d1v;
        sl += __shfl_xor_sync(0xffffffffu, sl, 1); sl += __shfl_xor_sync(0xffffffffu, sl, 2);
        dl += __shfl_xor_sync(0xffffffffu, dl, 1); dl += __shfl_xor_sync(0xffffffffu, dl, 2);
        sh += __shfl_xor_sync(0xffffffffu, sh, 1); sh += __shfl_xor_sync(0xffffffffu, sh, 2);
        dh += __shfl_xor_sync(0xffffffffu, dh, 1); dh += __shfl_xor_sync(0xffffffffu, dh, 2);
        if ((lane & 3) == 0) {
            if (vlo) { g_as1n[node_lo * 8 + tile] = sl; g_ad1n[node_lo * 8 + tile] = dl; }
            if (vhi) { g_as1n[node_hi * 8 + tile] = sh; g_ad1n[node_hi * 8 + tile] = dh; }
        }
    }
}

// ================= layer-1 aggregation: HALF-WARP per dst node ==============
// lanes 0-15 = node 2w, lanes 16-31 = node 2w+1.
// ALL shuffles use the per-half mask hm — the two halves have different trip
// counts and must be able to progress independently (FULL-mask here deadlocks).
__global__ __launch_bounds__(256) void agg1_kernel(const float* __restrict__ b1, int N)
{
    int gw = (blockIdx.x * blockDim.x + threadIdx.x) >> 5;
    int lane = threadIdx.x & 31;
    int hl   = lane & 15;
    int base = lane & 16;
    unsigned hm = 0xffffu << base;       // half-warp mask
    int node = gw * 2 + (base >> 4);
    bool vnode = node < N;
    int nc = vnode ? node : N - 1;
    int beg = g_rowptr[nc], end = g_rowptr[nc + 1];

    int head = hl & 7;
    int eg   = hl >> 3;      // 0/1: which edge of the pair this lane weighs
    int hq   = hl >> 1;      // head owning my 4 cols

    float adv = g_ad1n[(size_t)nc * 8 + head];
    float4 acc0 = {0,0,0,0}, acc1 = {0,0,0,0};
    float den = 0.0f;

    for (int pb = beg; pb < end; pb += 16) {
        int p = pb + hl;
        int myidx = (p < end) ? g_col[p] : 0;
        int cnt = min(16, end - pb);
        for (int k = 0; k < cnt; k += 2) {
            int ew = k + eg;
            int srcw = __shfl_sync(hm, myidx, base + (ew & 15));
            float w = 0.0f;
            if (ew < cnt) {
                w = __expf(lrelu(g_as1n[(size_t)srcw * 8 + head] + adv));
                den += w;
            }
            int s0 = __shfl_sync(hm, myidx, base + k);
            int s1 = __shfl_sync(hm, myidx, base + ((k + 1) & 15));
            float w0 = __shfl_sync(hm, w, base + hq);        // edge k   (eg=0 lanes)
            float w1 = __shfl_sync(hm, w, base + 8 + hq);    // edge k+1 (eg=1 lanes; 0 if invalid)
            uint2 u0 = ((const uint2*)(g_h1 + (size_t)s0 * HID))[hl];
            float2 p00 = __half22float2(*(__half2*)&u0.x);
            float2 p01 = __half22float2(*(__half2*)&u0.y);
            acc0.x = fmaf(w0, p00.x, acc0.x); acc0.y = fmaf(w0, p00.y, acc0.y);
            acc0.z = fmaf(w0, p01.x, acc0.z); acc0.w = fmaf(w0, p01.y, acc0.w);
            uint2 u1 = ((const uint2*)(g_h1 + (size_t)s1 * HID))[hl];
            float2 p10 = __half22float2(*(__half2*)&u1.x);
            float2 p11 = __half22float2(*(__half2*)&u1.y);
            acc1.x = fmaf(w1, p10.x, acc1.x); acc1.y = fmaf(w1, p10.y, acc1.y);
            acc1.z = fmaf(w1, p11.x, acc1.z); acc1.w = fmaf(w1, p11.y, acc1.w);
        }
    }
    // den per (eg, head) -> combine eg (xor 8 stays in half)
    den += __shfl_xor_sync(hm, den, 8);
    float dsum = __shfl_sync(hm, den, base + hq);

    if (vnode) {
        float4 bq = ((const float4*)b1)[hl];
        float inv = 1.0f / (dsum + 1e-16f);
        float4 v;
        v.x = (acc0.x + acc1.x) * inv + bq.x;
        v.y = (acc0.y + acc1.y) * inv + bq.y;
        v.z = (acc0.z + acc1.z) * inv + bq.z;
        v.w = (acc0.w + acc1.w) * inv + bq.w;
        v.x = v.x > 0.0f ? v.x : expm1f(v.x);
        v.y = v.y > 0.0f ? v.y : expm1f(v.y);
        v.z = v.z > 0.0f ? v.z : expm1f(v.z);
        v.w = v.w > 0.0f ? v.w : expm1f(v.w);
        ((float4*)(g_hx + (size_t)node * HID))[hl] = v;
    }
}

// ================= GEMM 2: h2 = hx @ W2 (fp16 out) ; node alphas =============
#define SX2_P4 17
__global__ __launch_bounds__(512) void gemm2_kernel(
    const float* __restrict__ W2,
    const float* __restrict__ as2, const float* __restrict__ ad2, int N)
{
    extern __shared__ float smem[];
    float*  sW  = smem;                        // 4096 floats
    float4* sXv = (float4*)(smem + HID * HID); // 256 rows x 17 float4

    int t = threadIdx.x;
    #pragma unroll
    for (int i = t; i < HID * HID / 4; i += 512)
        ((float4*)sW)[i] = ((const float4*)W2)[i];

    int nodeBase = blockIdx.x * 256;
    int rows = min(256, N - nodeBase);
    for (int i = t; i < rows * 16; i += 512) {
        int r = i >> 4, c = i & 15;
        sXv[r * SX2_P4 + c] = ((const float4*)(g_hx + (size_t)nodeBase * HID))[i];
    }
    __syncthreads();

    int j = t & 15;
    int g = t >> 4;

    ull acc[8][2];
    #pragma unroll
    for (int i = 0; i < 8; i++) { acc[i][0] = 0; acc[i][1] = 0; }

    #pragma unroll 4
    for (int k4 = 0; k4 < HID / 4; k4++) {
        float4 xv[8];
        #pragma unroll
        for (int i = 0; i < 8; i++) xv[i] = sXv[(g + 32 * i) * SX2_P4 + k4];
        #pragma unroll
        for (int kk = 0; kk < 4; kk++) {
            const ull* wr = (const ull*)(sW + (k4 * 4 + kk) * HID + j * 4);
            ull w0 = wr[0], w1 = wr[1];
            #pragma unroll
            for (int i = 0; i < 8; i++) {
                float xs = f4elem(xv[i], kk);
                ull xx = pack2(xs, xs);
                acc[i][0] = fma2(xx, w0, acc[i][0]);
                acc[i][1] = fma2(xx, w1, acc[i][1]);
            }
        }
    }

    #pragma unroll
    for (int i = 0; i < 8; i++) {
        int node = nodeBase + g + 32 * i;
        bool valid = node < N;
        float a[4];
        unpack2(acc[i][0], a[0], a[1]); unpack2(acc[i][1], a[2], a[3]);
        float s = 0.0f, d = 0.0f;
        #pragma unroll
        for (int c = 0; c < 4; c++) {
            s = fmaf(a[c], as2[j * 4 + c], s);
            d = fmaf(a[c], ad2[j * 4 + c], d);
        }
        #pragma unroll
        for (int o = 1; o < 16; o <<= 1) {
            s += __shfl_xor_sync(0xffffffffu, s, o);
            d += __shfl_xor_sync(0xffffffffu, d, o);
        }
        if (valid) {
            ((uint2*)(g_h2 + (size_t)node * HID))[j] = to_h4(a[0], a[1], a[2], a[3]);
            if (j == 0) { g_as2n[node] = s; g_ad2n[node] = d; }
        }
    }
}

// ================= layer-2 aggregation: HALF-WARP per dst node ==============
__global__ __launch_bounds__(256) void agg2_kernel(const float* __restrict__ b2, int N)
{
    int gw = (blockIdx.x * blockDim.x + threadIdx.x) >> 5;
    int lane = threadIdx.x & 31;
    int hl   = lane & 15;
    int base = lane & 16;
    unsigned hm = 0xffffu << base;       // half-warp mask
    int node = gw * 2 + (base >> 4);
    bool vnode = node < N;
    int nc = vnode ? node : N - 1;
    int beg = g_rowptr[nc], end = g_rowptr[nc + 1];

    float adv = g_ad2n[nc];
    float4 acc0 = {0,0,0,0}, acc1 = {0,0,0,0};
    float den = 0.0f;

    for (int pb = beg; pb < end; pb += 16) {
        int p = pb + hl;
        bool v = p < end;
        int myidx = v ? g_col[p] : 0;
        float wl = v ? __expf(lrelu(g_as2n[myidx] + adv)) : 0.0f;
        den += wl;
        int cnt = min(16, end - pb);
        for (int k = 0; k < cnt; k += 2) {
            int s0 = __shfl_sync(hm, myidx, base + k);
            int s1 = __shfl_sync(hm, myidx, base + ((k + 1) & 15));
            float w0 = __shfl_sync(hm, wl, base + k);
            float w1 = __shfl_sync(hm, wl, base + ((k + 1) & 15));
            if (k + 1 >= cnt) w1 = 0.0f;   // tail guard
            uint2 u0 = ((const uint2*)(g_h2 + (size_t)s0 * HID))[hl];
            float2 p00 = __half22float2(*(__half2*)&u0.x);
            float2 p01 = __half22float2(*(__half2*)&u0.y);
            acc0.x = fmaf(w0, p00.x, acc0.x); acc0.y = fmaf(w0, p00.y, acc0.y);
            acc0.z = fmaf(w0, p01.x, acc0.z); acc0.w = fmaf(w0, p01.y, acc0.w);
            uint2 u1 = ((const uint2*)(g_h2 + (size_t)s1 * HID))[hl];
            float2 p10 = __half22float2(*(__half2*)&u1.x);
            float2 p11 = __half22float2(*(__half2*)&u1.y);
            acc1.x = fmaf(w1, p10.x, acc1.x); acc1.y = fmaf(w1, p10.y, acc1.y);
            acc1.z = fmaf(w1, p11.x, acc1.z); acc1.w = fmaf(w1, p11.y, acc1.w);
        }
    }
    // den reduce within half (xor <= 8)
    den += __shfl_xor_sync(hm, den, 1);
    den += __shfl_xor_sync(hm, den, 2);
    den += __shfl_xor_sync(hm, den, 4);
    den += __shfl_xor_sync(hm, den, 8);

    if (vnode) {
        float4 bq = ((const float4*)b2)[hl];
        float inv = 1.0f / (den + 1e-16f);
        float4 zv;
        zv.x = (acc0.x + acc1.x) * inv + bq.x;
        zv.y = (acc0.y + acc1.y) * inv + bq.y;
        zv.z = (acc0.z + acc1.z) * inv + bq.z;
        zv.w = (acc0.w + acc1.w) * inv + bq.w;
        ((float4*)(g_z + (size_t)node * HID))[hl] = zv;
    }
}

// ================= decode + g_cnt reset =================
__global__ __launch_bounds__(256) void decode_kernel(
    const int* __restrict__ qe, float* __restrict__ out, int Q, int N)
{
    long long gid = (long long)blockIdx.x * blockDim.x + threadIdx.x;
    if (gid < N) g_cnt[(int)gid] = 0;
    int q = (int)(gid >> 3);
    int j = (int)(gid & 7);
    bool valid = q < Q;
    int qc = valid ? q : 0;
    int a = clampi(qe[qc], N);
    int b = clampi(qe[(size_t)Q + qc], N);
    const float4* za = (const float4*)(g_z + (size_t)a * HID + j * 8);
    const float4* zb = (const float4*)(g_z + (size_t)b * HID + j * 8);
    float4 a0 = za[0], a1 = za[1], b0 = zb[0], b1 = zb[1];
    float dot = a0.x * b0.x + a0.y * b0.y + a0.z * b0.z + a0.w * b0.w
              + a1.x * b1.x + a1.y * b1.y + a1.z * b1.z + a1.w * b1.w;
    #pragma unroll
    for (int o = 1; o < 8; o <<= 1) dot += __shfl_xor_sync(0xffffffffu, dot, o);
    if (valid && j == 0) out[q] = 1.0f / (1.0f + __expf(-dot));
}

// ================= launch =================
extern "C" void kernel_launch(void* const* d_in, const int* in_sizes, int n_in,
                              void* d_out, int out_size)
{
    const float* x   = (const float*)d_in[0];
    const int*   ei  = (const int*)d_in[1];
    const int*   qe  = (const int*)d_in[2];
    const float* W1  = (const float*)d_in[3];
    const float* as1 = (const float*)d_in[4];
    const float* ad1 = (const float*)d_in[5];
    const float* b1  = (const float*)d_in[6];
    const float* W2  = (const float*)d_in[7];
    const float* as2 = (const float*)d_in[8];
    const float* ad2 = (const float*)d_in[9];
    const float* b2  = (const float*)d_in[10];
    float*       out = (float*)d_out;

    int N = in_sizes[0] / DIM1;   // 100000
    int E = in_sizes[1] / 2;      // 1600000
    int Q = in_sizes[2] / 2;      // 100000
    int Etot = E + N;

    const int T = 256;
    int gN     = (N + T - 1) / T;
    int gE     = (E + T - 1) / T;
    int gGemm1 = (N + 127) / 128;
    int gGemm2 = (N + 255) / 256;
    long long aggThreads = (long long)((N + 1) / 2) * 32;   // half-warp per node
    int gAgg   = (int)((aggThreads + T - 1) / T);
    int gDec   = (int)(((long long)Q * 8 + T - 1) / T);
    int nChunks = (N + 1023) / 1024;

    const int SMEM1 = (128 * SA_PITCH + 128 * SB_PITCH) * 2;   // 53,248 B
    const int SMEM2 = (HID * HID + 256 * SX2_P4 * 4) * 4;      // 86,016 B
    cudaFuncSetAttribute(gemm1_kernel, cudaFuncAttributeMaxDynamicSharedMemorySize, SMEM1);
    cudaFuncSetAttribute(gemm2_kernel, cudaFuncAttributeMaxDynamicSharedMemorySize, SMEM2);

    static cudaStream_t s2 = nullptr;
    static cudaEvent_t evFork = nullptr, evJoin = nullptr;
    if (!s2) {
        cudaStreamCreate(&s2);
        cudaEventCreateWithFlags(&evFork, cudaEventDisableTiming);
        cudaEventCreateWithFlags(&evJoin, cudaEventDisableTiming);
    }

    // fork: CSR build on s2, gemm1 on main stream (disjoint data)
    cudaEventRecord(evFork, 0);
    cudaStreamWaitEvent(s2, evFork, 0);

    count_kernel<<<gE, T, 0, s2>>>(ei, E, N);
    scan1_kernel<<<nChunks, 1024, 0, s2>>>(N);
    scan3_kernel<<<gN, T, 0, s2>>>(N, Etot, nChunks);
    scatter_kernel<<<gE, T, 0, s2>>>(ei, E, N);
    cudaEventRecord(evJoin, s2);

    gemm1_kernel<<<gGemm1, T, SMEM1>>>(x, W1, as1, ad1, N);

    cudaStreamWaitEvent(0, evJoin, 0);

    agg1_kernel<<<gAgg, T>>>(b1, N);
    gemm2_kernel<<<gGemm2, 512, SMEM2>>>(W2, as2, ad2, N);
    agg2_kernel<<<gAgg, T>>>(b2, N);
    decode_kernel<<<gDec, T>>>(qe, out, Q, N);
}

// round 15
// speedup vs baseline: 1.0228x; 1.0228x over previous
#include <cuda_runtime.h>
#include <cuda_fp16.h>
#include <math.h>

#define NMAX 100000
#define EMAX 1700000
#define DIM1 128
#define HID  64

// ---------------- device scratch ----------------
__device__ __align__(16) __half g_h1[NMAX * HID];   // fp16 features (layer1)
__device__ __align__(16) __half g_h2[NMAX * HID];   // fp16 features (layer2)
__device__ __align__(16) float g_as1n[NMAX * 8];
__device__ __align__(16) float g_ad1n[NMAX * 8];
__device__ __align__(16) float g_hx  [NMAX * HID];
__device__ __align__(16) float g_as2n[NMAX];
__device__ __align__(16) float g_ad2n[NMAX];
__device__ __align__(16) float g_z   [NMAX * HID];
// CSR
__device__ int g_cnt   [NMAX];                       // counts -> cursors (reset by decode)
__device__ int g_rowptr[NMAX + 1];
__device__ int g_col   [EMAX];
__device__ unsigned long long g_state[128];          // lookback scan states (reset by decode)

// ---------------- helpers ----------------
__device__ __forceinline__ int clampi(int i, int N) {
    i = i < 0 ? 0 : i;
    return i >= N ? N - 1 : i;
}
__device__ __forceinline__ float lrelu(float v) { return v > 0.0f ? v : 0.2f * v; }

typedef unsigned long long ull;
__device__ __forceinline__ uint2 to_h4(float a0, float a1, float a2, float a3) {
    __half2 p0 = __float22half2_rn(make_float2(a0, a1));
    __half2 p1 = __float22half2_rn(make_float2(a2, a3));
    uint2 u;
    u.x = *(unsigned*)&p0;
    u.y = *(unsigned*)&p1;
    return u;
}
// tensor-core primitives
__device__ __forceinline__ void ldsm_x4(unsigned& r0, unsigned& r1, unsigned& r2, unsigned& r3, unsigned a) {
    asm volatile("ldmatrix.sync.aligned.m8n8.x4.shared.b16 {%0,%1,%2,%3}, [%4];"
                 : "=r"(r0), "=r"(r1), "=r"(r2), "=r"(r3) : "r"(a));
}
__device__ __forceinline__ void ldsm_x4t(unsigned& r0, unsigned& r1, unsigned& r2, unsigned& r3, unsigned a) {
    asm volatile("ldmatrix.sync.aligned.m8n8.x4.trans.shared.b16 {%0,%1,%2,%3}, [%4];"
                 : "=r"(r0), "=r"(r1), "=r"(r2), "=r"(r3) : "r"(a));
}
__device__ __forceinline__ void mma16816(float* c, unsigned a0, unsigned a1, unsigned a2, unsigned a3,
                                         unsigned b0, unsigned b1) {
    asm volatile("mma.sync.aligned.m16n8k16.row.col.f32.f16.f16.f32 "
                 "{%0,%1,%2,%3}, {%4,%5,%6,%7}, {%8,%9}, {%0,%1,%2,%3};"
                 : "+f"(c[0]), "+f"(c[1]), "+f"(c[2]), "+f"(c[3])
                 : "r"(a0), "r"(a1), "r"(a2), "r"(a3), "r"(b0), "r"(b1));
}

// ================= GEMM 1 (tensor cores) + fused edge count =================
// Launch #1. Edge-count atomics are independent of the MMA work and overlap it.
#define SA_PITCH 136
#define SB_PITCH 72
__global__ __launch_bounds__(256) void gemm1_kernel(
    const float* __restrict__ x, const float* __restrict__ W1,
    const float* __restrict__ as1, const float* __restrict__ ad1,
    const int* __restrict__ ei, int E, int N)
{
    extern __shared__ __half smh[];
    __half* sA = smh;                     // 128 x 136 halves
    __half* sB = smh + 128 * SA_PITCH;    // 128 x 72 halves

    int t = threadIdx.x;

    // fused count: fire-and-forget atomics (grid-stride over dst indices)
    for (long long ii = (long long)blockIdx.x * 256 + t; ii < E; ii += (long long)gridDim.x * 256)
        atomicAdd(&g_cnt[clampi(ei[(size_t)E + ii], N)], 1);

    int nodeBase = blockIdx.x * 128;
    int rows = min(128, N - nodeBase);

    for (int i = t; i < 128 * 16; i += 256) {
        int r = i >> 4, c4 = i & 15;
        float4 v = ((const float4*)W1)[i];
        *(uint2*)&sB[r * SB_PITCH + c4 * 4] = to_h4(v.x, v.y, v.z, v.w);
    }
    for (int i = t; i < 128 * 32; i += 256) {
        int r = i >> 5, c4 = i & 31;
        float4 v = make_float4(0.f, 0.f, 0.f, 0.f);
        if (r < rows) v = ((const float4*)(x + (size_t)nodeBase * DIM1))[i];
        *(uint2*)&sA[r * SA_PITCH + c4 * 4] = to_h4(v.x, v.y, v.z, v.w);
    }
    __syncthreads();

    int w = t >> 5, lane = t & 31;
    unsigned sAc = (unsigned)__cvta_generic_to_shared(sA);
    unsigned sBc = (unsigned)__cvta_generic_to_shared(sB);
    unsigned aBase = sAc + ((16 * w + (lane & 15)) * SA_PITCH + (lane >> 4) * 8) * 2;
    unsigned bLane = sBc + ((lane & 15) * SB_PITCH + (lane >> 4) * 8) * 2;

    float acc[8][4];
    #pragma unroll
    for (int nt = 0; nt < 8; nt++)
        #pragma unroll
        for (int m = 0; m < 4; m++) acc[nt][m] = 0.0f;

    #pragma unroll
    for (int s = 0; s < 8; s++) {
        unsigned a0, a1, a2, a3;
        ldsm_x4(a0, a1, a2, a3, aBase + s * 32);
        unsigned bStep = bLane + s * 16 * SB_PITCH * 2;
        #pragma unroll
        for (int nt = 0; nt < 8; nt += 2) {
            unsigned b0, b1, b2, b3;
            ldsm_x4t(b0, b1, b2, b3, bStep + nt * 16);
            mma16816(acc[nt],     a0, a1, a2, a3, b0, b1);
            mma16816(acc[nt + 1], a0, a1, a2, a3, b2, b3);
        }
    }

    int r_lo = 16 * w + (lane >> 2);
    int node_lo = nodeBase + r_lo;
    int node_hi = node_lo + 8;
    int c2i = (lane & 3) * 2;
    bool vlo = node_lo < N, vhi = node_hi < N;

    #pragma unroll
    for (int tile = 0; tile < 8; tile++) {
        int col = tile * 8 + c2i;
        float a0v = acc[tile][0], a1v = acc[tile][1];
        float a2v = acc[tile][2], a3v = acc[tile][3];
        if (vlo) {
            __half2 hv = __float22half2_rn(make_float2(a0v, a1v));
            *(__half2*)&g_h1[(size_t)node_lo * HID + col] = hv;
        }
        if (vhi) {
            __half2 hv = __float22half2_rn(make_float2(a2v, a3v));
            *(__half2*)&g_h1[(size_t)node_hi * HID + col] = hv;
        }
        float s0 = as1[col], s1v = as1[col + 1];
        float d0 = ad1[col], d1v = ad1[col + 1];
        float sl = a0v * s0 + a1v * s1v, dl = a0v * d0 + a1v * d1v;
        float sh = a2v * s0 + a3v * s1v, dh = a2v * d0 + a3v * d1v;
        sl += __shfl_xor_sync(0xffffffffu, sl, 1); sl += __shfl_xor_sync(0xffffffffu, sl, 2);
        dl += __shfl_xor_sync(0xffffffffu, dl, 1); dl += __shfl_xor_sync(0xffffffffu, dl, 2);
        sh += __shfl_xor_sync(0xffffffffu, sh, 1); sh += __shfl_xor_sync(0xffffffffu, sh, 2);
        dh += __shfl_xor_sync(0xffffffffu, dh, 1); dh += __shfl_xor_sync(0xffffffffu, dh, 2);
        if ((lane & 3) == 0) {
            if (vlo) { g_as1n[node_lo * 8 + tile] = sl; g_ad1n[node_lo * 8 + tile] = dl; }
            if (vhi) { g_as1n[node_hi * 8 + tile] = sh; g_ad1n[node_hi * 8 + tile] = dh; }
        }
    }
}

// ================= single-pass scan (decoupled lookback) =====================
// 98 blocks x 1024 threads, all co-resident (98 <= 148 SMs) -> no deadlock.
// Produces rowptr (exclusive + self-loops), seeds self-loop, inits cursors.
__global__ __launch_bounds__(1024) void scan_kernel(int N, int Etot) {
    __shared__ int warpsum[32];
    __shared__ int s_boff;
    const unsigned FULL = 0xffffffffu;
    int b = blockIdx.x, t = threadIdx.x;
    int lane = t & 31, wid = t >> 5;
    int i = b * 1024 + t;
    int v = (i < N) ? g_cnt[i] : 0;

    // warp inclusive scan
    int xs = v;
    #pragma unroll
    for (int o = 1; o < 32; o <<= 1) {
        int y = __shfl_up_sync(FULL, xs, o);
        if (lane >= o) xs += y;
    }
    if (lane == 31) warpsum[wid] = xs;
    __syncthreads();
    if (wid == 0) {
        int s = warpsum[lane];
        #pragma unroll
        for (int o = 1; o < 32; o <<= 1) {
            int y = __shfl_up_sync(FULL, s, o);
            if (lane >= o) s += y;
        }
        warpsum[lane] = s;
    }
    __syncthreads();
    int incl = xs + (wid > 0 ? warpsum[wid - 1] : 0);
    int blocktot = warpsum[31];

    if (t == 0) {
        if (b == 0) {
            atomicExch(&g_state[0], ((ull)(unsigned)blocktot << 2) | 2ull);
            s_boff = 0;
        } else {
            atomicExch(&g_state[b], ((ull)(unsigned)blocktot << 2) | 1ull);
            int off = 0, p = b - 1;
            while (true) {
                ull s = atomicAdd(&g_state[p], 0ull);
                int st = (int)(s & 3ull);
                if (st == 0) continue;               // not published yet
                off += (int)(s >> 2);
                if (st == 2) break;                  // inclusive found
                p--;
            }
            atomicExch(&g_state[b], ((ull)(unsigned)(off + blocktot) << 2) | 2ull);
            s_boff = off;
        }
    }
    __syncthreads();
    int boff = s_boff;

    if (i < N) {
        int rp = (incl - v) + boff + i;   // exclusive scan + i self-loops before i
        g_rowptr[i] = rp;
        g_col[rp] = i;                    // self loop first in segment
        g_cnt[i] = rp + 1;                // scatter cursor
    }
    if (i == 0) g_rowptr[N] = Etot;
}

__global__ void scatter_kernel(const int* __restrict__ ei, int E, int N) {
    int i = blockIdx.x * blockDim.x + threadIdx.x;
    if (i >= E) return;
    int src = clampi(ei[i], N);
    int dst = clampi(ei[(size_t)E + i], N);
    int pos = atomicAdd(&g_cnt[dst], 1);
    g_col[pos] = src;
}

// ================= layer-1 aggregation: warp per dst (best known, R12) =======
__global__ __launch_bounds__(256) void agg1_kernel(const float* __restrict__ b1, int N)
{
    const unsigned FULL = 0xffffffffu;
    int warp = (blockIdx.x * blockDim.x + threadIdx.x) >> 5;
    int lane = threadIdx.x & 31;
    if (warp >= N) return;
    int beg = g_rowptr[warp], end = g_rowptr[warp + 1];

    int head8 = lane & 7;
    int grp   = lane >> 3;
    int half  = lane >> 4;
    int q     = lane & 15;
    int hq    = q >> 1;

    float adv = g_ad1n[(size_t)warp * 8 + head8];
    float4 accA = {0,0,0,0}, accB = {0,0,0,0};
    float den = 0.0f;

    for (int pb = beg; pb < end; pb += 32) {
        int p = pb + lane;
        int myidx = (p < end) ? g_col[p] : 0;
        int cnt = min(32, end - pb);
        for (int k = 0; k < cnt; k += 4) {
            int eg = k + grp;
            int srcg = __shfl_sync(FULL, myidx, eg);
            float w = 0.0f;
            if (eg < cnt) {
                w = __expf(lrelu(g_as1n[(size_t)srcg * 8 + head8] + adv));
                den += w;
            }
            int s0 = __shfl_sync(FULL, myidx, k + half);
            int s1 = __shfl_sync(FULL, myidx, k + 2 + half);
            float w0 = __shfl_sync(FULL, w, half * 8 + hq);
            float w1 = __shfl_sync(FULL, w, (2 + half) * 8 + hq);
            uint2 u0 = ((const uint2*)(g_h1 + (size_t)s0 * HID))[q];
            float2 p00 = __half22float2(*(__half2*)&u0.x);
            float2 p01 = __half22float2(*(__half2*)&u0.y);
            accA.x = fmaf(w0, p00.x, accA.x); accA.y = fmaf(w0, p00.y, accA.y);
            accA.z = fmaf(w0, p01.x, accA.z); accA.w = fmaf(w0, p01.y, accA.w);
            uint2 u1 = ((const uint2*)(g_h1 + (size_t)s1 * HID))[q];
            float2 p10 = __half22float2(*(__half2*)&u1.x);
            float2 p11 = __half22float2(*(__half2*)&u1.y);
            accB.x = fmaf(w1, p10.x, accB.x); accB.y = fmaf(w1, p10.y, accB.y);
            accB.z = fmaf(w1, p11.x, accB.z); accB.w = fmaf(w1, p11.y, accB.w);
        }
    }
    den += __shfl_xor_sync(FULL, den, 8);
    den += __shfl_xor_sync(FULL, den, 16);
    float dsum = __shfl_sync(FULL, den, hq);

    float4 acc;
    acc.x = accA.x + accB.x; acc.y = accA.y + accB.y;
    acc.z = accA.z + accB.z; acc.w = accA.w + accB.w;
    acc.x += __shfl_xor_sync(FULL, acc.x, 16);
    acc.y += __shfl_xor_sync(FULL, acc.y, 16);
    acc.z += __shfl_xor_sync(FULL, acc.z, 16);
    acc.w += __shfl_xor_sync(FULL, acc.w, 16);

    if (half == 0) {
        float4 bq = ((const float4*)b1)[q];
        float inv = 1.0f / (dsum + 1e-16f);
        float4 v;
        v.x = acc.x * inv + bq.x; v.y = acc.y * inv + bq.y;
        v.z = acc.z * inv + bq.z; v.w = acc.w * inv + bq.w;
        v.x = v.x > 0.0f ? v.x : expm1f(v.x);
        v.y = v.y > 0.0f ? v.y : expm1f(v.y);
        v.z = v.z > 0.0f ? v.z : expm1f(v.z);
        v.w = v.w > 0.0f ? v.w : expm1f(v.w);
        ((float4*)(g_hx + (size_t)warp * HID))[q] = v;
    }
}

// ================= GEMM 2: h2 = hx @ W2 (fp16 out) ; node alphas =============
__device__ __forceinline__ float f4elem(float4 v, int kk) {
    return kk == 0 ? v.x : kk == 1 ? v.y : kk == 2 ? v.z : v.w;
}
__device__ __forceinline__ ull pack2(float lo, float hi) {
    ull r; asm("mov.b64 %0,{%1,%2};" : "=l"(r) : "f"(lo), "f"(hi)); return r;
}
__device__ __forceinline__ void unpack2(ull v, float& lo, float& hi) {
    asm("mov.b64 {%0,%1},%2;" : "=f"(lo), "=f"(hi) : "l"(v));
}
__device__ __forceinline__ ull fma2(ull a, ull b, ull c) {
    ull d; asm("fma.rn.f32x2 %0,%1,%2,%3;" : "=l"(d) : "l"(a), "l"(b), "l"(c)); return d;
}
#define SX2_P4 17
__global__ __launch_bounds__(512) void gemm2_kernel(
    const float* __restrict__ W2,
    const float* __restrict__ as2, const float* __restrict__ ad2, int N)
{
    extern __shared__ float smem[];
    float*  sW  = smem;                        // 4096 floats
    float4* sXv = (float4*)(smem + HID * HID); // 256 rows x 17 float4

    int t = threadIdx.x;
    #pragma unroll
    for (int i = t; i < HID * HID / 4; i += 512)
        ((float4*)sW)[i] = ((const float4*)W2)[i];

    int nodeBase = blockIdx.x * 256;
    int rows = min(256, N - nodeBase);
    for (int i = t; i < rows * 16; i += 512) {
        int r = i >> 4, c = i & 15;
        sXv[r * SX2_P4 + c] = ((const float4*)(g_hx + (size_t)nodeBase * HID))[i];
    }
    __syncthreads();

    int j = t & 15;
    int g = t >> 4;

    ull acc[8][2];
    #pragma unroll
    for (int i = 0; i < 8; i++) { acc[i][0] = 0; acc[i][1] = 0; }

    #pragma unroll 4
    for (int k4 = 0; k4 < HID / 4; k4++) {
        float4 xv[8];
        #pragma unroll
        for (int i = 0; i < 8; i++) xv[i] = sXv[(g + 32 * i) * SX2_P4 + k4];
        #pragma unroll
        for (int kk = 0; kk < 4; kk++) {
            const ull* wr = (const ull*)(sW + (k4 * 4 + kk) * HID + j * 4);
            ull w0 = wr[0], w1 = wr[1];
            #pragma unroll
            for (int i = 0; i < 8; i++) {
                float xs = f4elem(xv[i], kk);
                ull xx = pack2(xs, xs);
                acc[i][0] = fma2(xx, w0, acc[i][0]);
                acc[i][1] = fma2(xx, w1, acc[i][1]);
            }
        }
    }

    #pragma unroll
    for (int i = 0; i < 8; i++) {
        int node = nodeBase + g + 32 * i;
        bool valid = node < N;
        float a[4];
        unpack2(acc[i][0], a[0], a[1]); unpack2(acc[i][1], a[2], a[3]);
        float s = 0.0f, d = 0.0f;
        #pragma unroll
        for (int c = 0; c < 4; c++) {
            s = fmaf(a[c], as2[j * 4 + c], s);
            d = fmaf(a[c], ad2[j * 4 + c], d);
        }
        #pragma unroll
        for (int o = 1; o < 16; o <<= 1) {
            s += __shfl_xor_sync(0xffffffffu, s, o);
            d += __shfl_xor_sync(0xffffffffu, d, o);
        }
        if (valid) {
            ((uint2*)(g_h2 + (size_t)node * HID))[j] = to_h4(a[0], a[1], a[2], a[3]);
            if (j == 0) { g_as2n[node] = s; g_ad2n[node] = d; }
        }
    }
}

// ================= layer-2 aggregation: warp per dst (best known, R12) =======
__global__ __launch_bounds__(256) void agg2_kernel(const float* __restrict__ b2, int N)
{
    const unsigned FULL = 0xffffffffu;
    int warp = (blockIdx.x * blockDim.x + threadIdx.x) >> 5;
    int lane = threadIdx.x & 31;
    if (warp >= N) return;
    int beg = g_rowptr[warp], end = g_rowptr[warp + 1];

    int half = lane >> 4, q = lane & 15;
    float adv = g_ad2n[warp];
    float4 accA = {0,0,0,0}, accB = {0,0,0,0};
    float den = 0.0f;

    for (int pb = beg; pb < end; pb += 32) {
        int p = pb + lane;
        bool v = p < end;
        int myidx = v ? g_col[p] : 0;
        float wl = v ? __expf(lrelu(g_as2n[myidx] + adv)) : 0.0f;
        den += wl;
        int cnt = min(32, end - pb);
        for (int k = 0; k < cnt; k += 4) {
            int s0 = __shfl_sync(FULL, myidx, k + half);
            int s1 = __shfl_sync(FULL, myidx, k + 2 + half);
            float w0 = __shfl_sync(FULL, wl, k + half);
            float w1 = __shfl_sync(FULL, wl, k + 2 + half);
            uint2 u0 = ((const uint2*)(g_h2 + (size_t)s0 * HID))[q];
            float2 p00 = __half22float2(*(__half2*)&u0.x);
            float2 p01 = __half22float2(*(__half2*)&u0.y);
            accA.x = fmaf(w0, p00.x, accA.x); accA.y = fmaf(w0, p00.y, accA.y);
            accA.z = fmaf(w0, p01.x, accA.z); accA.w = fmaf(w0, p01.y, accA.w);
            uint2 u1 = ((const uint2*)(g_h2 + (size_t)s1 * HID))[q];
            float2 p10 = __half22float2(*(__half2*)&u1.x);
            float2 p11 = __half22float2(*(__half2*)&u1.y);
            accB.x = fmaf(w1, p10.x, accB.x); accB.y = fmaf(w1, p10.y, accB.y);
            accB.z = fmaf(w1, p11.x, accB.z); accB.w = fmaf(w1, p11.y, accB.w);
        }
    }
    #pragma unroll
    for (int o = 1; o < 32; o <<= 1) den += __shfl_xor_sync(FULL, den, o);

    float4 acc;
    acc.x = accA.x + accB.x; acc.y = accA.y + accB.y;
    acc.z = accA.z + accB.z; acc.w = accA.w + accB.w;
    acc.x += __shfl_xor_sync(FULL, acc.x, 16);
    acc.y += __shfl_xor_sync(FULL, acc.y, 16);
    acc.z += __shfl_xor_sync(FULL, acc.z, 16);
    acc.w += __shfl_xor_sync(FULL, acc.w, 16);

    if (half == 0) {
        float4 bq = ((const float4*)b2)[q];
        float inv = 1.0f / (den + 1e-16f);
        float4 zv;
        zv.x = acc.x * inv + bq.x; zv.y = acc.y * inv + bq.y;
        zv.z = acc.z * inv + bq.z; zv.w = acc.w * inv + bq.w;
        ((float4*)(g_z + (size_t)warp * HID))[q] = zv;
    }
}

// ================= decode + state reset =================
__global__ __launch_bounds__(256) void decode_kernel(
    const int* __restrict__ qe, float* __restrict__ out, int Q, int N)
{
    long long gid = (long long)blockIdx.x * blockDim.x + threadIdx.x;
    if (gid < N) g_cnt[(int)gid] = 0;
    if (gid < 128) g_state[(int)gid] = 0ull;
    int q = (int)(gid >> 3);
    int j = (int)(gid & 7);
    bool valid = q < Q;
    int qc = valid ? q : 0;
    int a = clampi(qe[qc], N);
    int b = clampi(qe[(size_t)Q + qc], N);
    const float4* za = (const float4*)(g_z + (size_t)a * HID + j * 8);
    const float4* zb = (const float4*)(g_z + (size_t)b * HID + j * 8);
    float4 a0 = za[0], a1 = za[1], b0 = zb[0], b1 = zb[1];
    float dot = a0.x * b0.x + a0.y * b0.y + a0.z * b0.z + a0.w * b0.w
              + a1.x * b1.x + a1.y * b1.y + a1.z * b1.z + a1.w * b1.w;
    #pragma unroll
    for (int o = 1; o < 8; o <<= 1) dot += __shfl_xor_sync(0xffffffffu, dot, o);
    if (valid && j == 0) out[q] = 1.0f / (1.0f + __expf(-dot));
}

// ================= launch =================
extern "C" void kernel_launch(void* const* d_in, const int* in_sizes, int n_in,
                              void* d_out, int out_size)
{
    const float* x   = (const float*)d_in[0];
    const int*   ei  = (const int*)d_in[1];
    const int*   qe  = (const int*)d_in[2];
    const float* W1  = (const float*)d_in[3];
    const float* as1 = (const float*)d_in[4];
    const float* ad1 = (const float*)d_in[5];
    const float* b1  = (const float*)d_in[6];
    const float* W2  = (const float*)d_in[7];
    const float* as2 = (const float*)d_in[8];
    const float* ad2 = (const float*)d_in[9];
    const float* b2  = (const float*)d_in[10];
    float*       out = (float*)d_out;

    int N = in_sizes[0] / DIM1;   // 100000
    int E = in_sizes[1] / 2;      // 1600000
    int Q = in_sizes[2] / 2;      // 100000
    int Etot = E + N;

    const int T = 256;
    int gE     = (E + T - 1) / T;
    int gGemm1 = (N + 127) / 128;
    int gGemm2 = (N + 255) / 256;
    int gWarp  = (N * 32 + T - 1) / T;
    int gDec   = (int)(((long long)Q * 8 + T - 1) / T);
    int nChunks = (N + 1023) / 1024;   // 98 <= 148 SMs: lookback-safe

    const int SMEM1 = (128 * SA_PITCH + 128 * SB_PITCH) * 2;   // 53,248 B
    const int SMEM2 = (HID * HID + 256 * SX2_P4 * 4) * 4;      // 86,016 B
    cudaFuncSetAttribute(gemm1_kernel, cudaFuncAttributeMaxDynamicSharedMemorySize, SMEM1);
    cudaFuncSetAttribute(gemm2_kernel, cudaFuncAttributeMaxDynamicSharedMemorySize, SMEM2);

    // single stream; agg1 is the 4th kernel launch (ncu capture slot)
    gemm1_kernel<<<gGemm1, T, SMEM1>>>(x, W1, as1, ad1, ei, E, N);  // + fused count
    scan_kernel<<<nChunks, 1024>>>(N, Etot);
    scatter_kernel<<<gE, T>>>(ei, E, N);
    agg1_kernel<<<gWarp, T>>>(b1, N);
    gemm2_kernel<<<gGemm2, 512, SMEM2>>>(W2, as2, ad2, N);
    agg2_kernel<<<gWarp, T>>>(b2, N);
    decode_kernel<<<gDec, T>>>(qe, out, Q, N);
}

// round 16
// speedup vs baseline: 1.0825x; 1.0584x over previous
#include <cuda_runtime.h>
#include <cuda_fp16.h>
#include <math.h>

#define NMAX 100000
#define EMAX 1700000
#define DIM1 128
#define HID  64

// ---------------- device scratch ----------------
__device__ __align__(16) __half g_h1[NMAX * HID];   // fp16 features (layer1)
__device__ __align__(16) __half g_h2[NMAX * HID];   // fp16 features (layer2)
__device__ __align__(16) float g_as1n[NMAX * 8];
__device__ __align__(16) float g_ad1n[NMAX * 8];
__device__ __align__(16) float g_hx  [NMAX * HID];
__device__ __align__(16) float g_as2n[NMAX];
__device__ __align__(16) float g_ad2n[NMAX];
__device__ __align__(16) float g_z   [NMAX * HID];
// CSR
__device__ int g_cnt   [NMAX];                       // counts -> cursors (reset by decode)
__device__ int g_rowptr[NMAX + 1];
__device__ int g_col   [EMAX];
__device__ unsigned long long g_state[128];          // lookback scan states (reset by decode)

// ---------------- helpers ----------------
__device__ __forceinline__ int clampi(int i, int N) {
    i = i < 0 ? 0 : i;
    return i >= N ? N - 1 : i;
}
__device__ __forceinline__ float lrelu(float v) { return v > 0.0f ? v : 0.2f * v; }

typedef unsigned long long ull;
__device__ __forceinline__ uint2 to_h4(float a0, float a1, float a2, float a3) {
    __half2 p0 = __float22half2_rn(make_float2(a0, a1));
    __half2 p1 = __float22half2_rn(make_float2(a2, a3));
    uint2 u;
    u.x = *(unsigned*)&p0;
    u.y = *(unsigned*)&p1;
    return u;
}
// tensor-core primitives
__device__ __forceinline__ void ldsm_x4(unsigned& r0, unsigned& r1, unsigned& r2, unsigned& r3, unsigned a) {
    asm volatile("ldmatrix.sync.aligned.m8n8.x4.shared.b16 {%0,%1,%2,%3}, [%4];"
                 : "=r"(r0), "=r"(r1), "=r"(r2), "=r"(r3) : "r"(a));
}
__device__ __forceinline__ void ldsm_x4t(unsigned& r0, unsigned& r1, unsigned& r2, unsigned& r3, unsigned a) {
    asm volatile("ldmatrix.sync.aligned.m8n8.x4.trans.shared.b16 {%0,%1,%2,%3}, [%4];"
                 : "=r"(r0), "=r"(r1), "=r"(r2), "=r"(r3) : "r"(a));
}
__device__ __forceinline__ void mma16816(float* c, unsigned a0, unsigned a1, unsigned a2, unsigned a3,
                                         unsigned b0, unsigned b1) {
    asm volatile("mma.sync.aligned.m16n8k16.row.col.f32.f16.f16.f32 "
                 "{%0,%1,%2,%3}, {%4,%5,%6,%7}, {%8,%9}, {%0,%1,%2,%3};"
                 : "+f"(c[0]), "+f"(c[1]), "+f"(c[2]), "+f"(c[3])
                 : "r"(a0), "r"(a1), "r"(a2), "r"(a3), "r"(b0), "r"(b1));
}

// ================= GEMM 1 (tensor cores) + fused edge count =================
#define SA_PITCH 136
#define SB_PITCH 72
__global__ __launch_bounds__(256) void gemm1_kernel(
    const float* __restrict__ x, const float* __restrict__ W1,
    const float* __restrict__ as1, const float* __restrict__ ad1,
    const int* __restrict__ ei, int E, int N)
{
    extern __shared__ __half smh[];
    __half* sA = smh;                     // 128 x 136 halves
    __half* sB = smh + 128 * SA_PITCH;    // 128 x 72 halves

    int t = threadIdx.x;

    // fused count: fire-and-forget atomics (grid-stride over dst indices)
    for (long long ii = (long long)blockIdx.x * 256 + t; ii < E; ii += (long long)gridDim.x * 256)
        atomicAdd(&g_cnt[clampi(ei[(size_t)E + ii], N)], 1);

    int nodeBase = blockIdx.x * 128;
    int rows = min(128, N - nodeBase);

    for (int i = t; i < 128 * 16; i += 256) {
        int r = i >> 4, c4 = i & 15;
        float4 v = ((const float4*)W1)[i];
        *(uint2*)&sB[r * SB_PITCH + c4 * 4] = to_h4(v.x, v.y, v.z, v.w);
    }
    for (int i = t; i < 128 * 32; i += 256) {
        int r = i >> 5, c4 = i & 31;
        float4 v = make_float4(0.f, 0.f, 0.f, 0.f);
        if (r < rows) v = ((const float4*)(x + (size_t)nodeBase * DIM1))[i];
        *(uint2*)&sA[r * SA_PITCH + c4 * 4] = to_h4(v.x, v.y, v.z, v.w);
    }
    __syncthreads();

    int w = t >> 5, lane = t & 31;
    unsigned sAc = (unsigned)__cvta_generic_to_shared(sA);
    unsigned sBc = (unsigned)__cvta_generic_to_shared(sB);
    unsigned aBase = sAc + ((16 * w + (lane & 15)) * SA_PITCH + (lane >> 4) * 8) * 2;
    unsigned bLane = sBc + ((lane & 15) * SB_PITCH + (lane >> 4) * 8) * 2;

    float acc[8][4];
    #pragma unroll
    for (int nt = 0; nt < 8; nt++)
        #pragma unroll
        for (int m = 0; m < 4; m++) acc[nt][m] = 0.0f;

    #pragma unroll
    for (int s = 0; s < 8; s++) {
        unsigned a0, a1, a2, a3;
        ldsm_x4(a0, a1, a2, a3, aBase + s * 32);
        unsigned bStep = bLane + s * 16 * SB_PITCH * 2;
        #pragma unroll
        for (int nt = 0; nt < 8; nt += 2) {
            unsigned b0, b1, b2, b3;
            ldsm_x4t(b0, b1, b2, b3, bStep + nt * 16);
            mma16816(acc[nt],     a0, a1, a2, a3, b0, b1);
            mma16816(acc[nt + 1], a0, a1, a2, a3, b2, b3);
        }
    }

    int r_lo = 16 * w + (lane >> 2);
    int node_lo = nodeBase + r_lo;
    int node_hi = node_lo + 8;
    int c2i = (lane & 3) * 2;
    bool vlo = node_lo < N, vhi = node_hi < N;

    #pragma unroll
    for (int tile = 0; tile < 8; tile++) {
        int col = tile * 8 + c2i;
        float a0v = acc[tile][0], a1v = acc[tile][1];
        float a2v = acc[tile][2], a3v = acc[tile][3];
        if (vlo) {
            __half2 hv = __float22half2_rn(make_float2(a0v, a1v));
            *(__half2*)&g_h1[(size_t)node_lo * HID + col] = hv;
        }
        if (vhi) {
            __half2 hv = __float22half2_rn(make_float2(a2v, a3v));
            *(__half2*)&g_h1[(size_t)node_hi * HID + col] = hv;
        }
        float s0 = as1[col], s1v = as1[col + 1];
        float d0 = ad1[col], d1v = ad1[col + 1];
        float sl = a0v * s0 + a1v * s1v, dl = a0v * d0 + a1v * d1v;
        float sh = a2v * s0 + a3v * s1v, dh = a2v * d0 + a3v * d1v;
        sl += __shfl_xor_sync(0xffffffffu, sl, 1); sl += __shfl_xor_sync(0xffffffffu, sl, 2);
        dl += __shfl_xor_sync(0xffffffffu, dl, 1); dl += __shfl_xor_sync(0xffffffffu, dl, 2);
        sh += __shfl_xor_sync(0xffffffffu, sh, 1); sh += __shfl_xor_sync(0xffffffffu, sh, 2);
        dh += __shfl_xor_sync(0xffffffffu, dh, 1); dh += __shfl_xor_sync(0xffffffffu, dh, 2);
        if ((lane & 3) == 0) {
            if (vlo) { g_as1n[node_lo * 8 + tile] = sl; g_ad1n[node_lo * 8 + tile] = dl; }
            if (vhi) { g_as1n[node_hi * 8 + tile] = sh; g_ad1n[node_hi * 8 + tile] = dh; }
        }
    }
}

// ================= single-pass scan (decoupled lookback) =====================
__global__ __launch_bounds__(1024) void scan_kernel(int N, int Etot) {
    __shared__ int warpsum[32];
    __shared__ int s_boff;
    const unsigned FULL = 0xffffffffu;
    int b = blockIdx.x, t = threadIdx.x;
    int lane = t & 31, wid = t >> 5;
    int i = b * 1024 + t;
    int v = (i < N) ? g_cnt[i] : 0;

    int xs = v;
    #pragma unroll
    for (int o = 1; o < 32; o <<= 1) {
        int y = __shfl_up_sync(FULL, xs, o);
        if (lane >= o) xs += y;
    }
    if (lane == 31) warpsum[wid] = xs;
    __syncthreads();
    if (wid == 0) {
        int s = warpsum[lane];
        #pragma unroll
        for (int o = 1; o < 32; o <<= 1) {
            int y = __shfl_up_sync(FULL, s, o);
            if (lane >= o) s += y;
        }
        warpsum[lane] = s;
    }
    __syncthreads();
    int incl = xs + (wid > 0 ? warpsum[wid - 1] : 0);
    int blocktot = warpsum[31];

    if (t == 0) {
        if (b == 0) {
            atomicExch(&g_state[0], ((ull)(unsigned)blocktot << 2) | 2ull);
            s_boff = 0;
        } else {
            atomicExch(&g_state[b], ((ull)(unsigned)blocktot << 2) | 1ull);
            int off = 0, p = b - 1;
            while (true) {
                ull s = atomicAdd(&g_state[p], 0ull);
                int st = (int)(s & 3ull);
                if (st == 0) continue;
                off += (int)(s >> 2);
                if (st == 2) break;
                p--;
            }
            atomicExch(&g_state[b], ((ull)(unsigned)(off + blocktot) << 2) | 2ull);
            s_boff = off;
        }
    }
    __syncthreads();
    int boff = s_boff;

    if (i < N) {
        int rp = (incl - v) + boff + i;   // exclusive scan + i self-loops before i
        g_rowptr[i] = rp;
        g_col[rp] = i;                    // self loop first in segment
        g_cnt[i] = rp + 1;                // scatter cursor
    }
    if (i == 0) g_rowptr[N] = Etot;
}

__global__ void scatter_kernel(const int* __restrict__ ei, int E, int N) {
    int i = blockIdx.x * blockDim.x + threadIdx.x;
    if (i >= E) return;
    int src = clampi(ei[i], N);
    int dst = clampi(ei[(size_t)E + i], N);
    int pos = atomicAdd(&g_cnt[dst], 1);
    g_col[pos] = src;
}

// ================= layer-1 aggregation: shuffle-free lane mapping ===========
// warp per dst node. lane = grp*8 + head: grp = edge slot (4 in flight),
// head = lane&7 owns cols head*8..head*8+7 = one uint4 of the fp16 row.
// The lane that computes w[edge=grp][head] consumes it directly — no shuffles
// in the hot path except the single edge-index broadcast.
__global__ __launch_bounds__(256) void agg1_kernel(const float* __restrict__ b1, int N)
{
    const unsigned FULL = 0xffffffffu;
    int warp = (blockIdx.x * blockDim.x + threadIdx.x) >> 5;
    int lane = threadIdx.x & 31;
    if (warp >= N) return;
    int beg = g_rowptr[warp], end = g_rowptr[warp + 1];

    int head = lane & 7;
    int grp  = lane >> 3;

    float adv = g_ad1n[(size_t)warp * 8 + head];
    float acc[8] = {0,0,0,0,0,0,0,0};
    float den = 0.0f;

    for (int pb = beg; pb < end; pb += 32) {
        int p = pb + lane;
        int myidx = (p < end) ? g_col[p] : 0;
        int cnt = min(32, end - pb);
        for (int k = 0; k < cnt; k += 4) {
            int eg = k + grp;
            int srcg = __shfl_sync(FULL, myidx, eg);   // eg <= 31 always
            float w = 0.0f;
            if (eg < cnt) {
                w = __expf(lrelu(g_as1n[srcg * 8 + head] + adv));
                den += w;
            }
            uint4 u = *(const uint4*)(g_h1 + ((size_t)(unsigned)srcg << 6) + (head << 3));
            float2 f0 = __half22float2(*(__half2*)&u.x);
            float2 f1 = __half22float2(*(__half2*)&u.y);
            float2 f2 = __half22float2(*(__half2*)&u.z);
            float2 f3 = __half22float2(*(__half2*)&u.w);
            acc[0] = fmaf(w, f0.x, acc[0]); acc[1] = fmaf(w, f0.y, acc[1]);
            acc[2] = fmaf(w, f1.x, acc[2]); acc[3] = fmaf(w, f1.y, acc[3]);
            acc[4] = fmaf(w, f2.x, acc[4]); acc[5] = fmaf(w, f2.y, acc[5]);
            acc[6] = fmaf(w, f3.x, acc[6]); acc[7] = fmaf(w, f3.y, acc[7]);
        }
    }
    // reduce over the 4 edge groups (lanes head, head+8, head+16, head+24)
    den += __shfl_xor_sync(FULL, den, 8);
    den += __shfl_xor_sync(FULL, den, 16);
    #pragma unroll
    for (int c = 0; c < 8; c++) {
        acc[c] += __shfl_xor_sync(FULL, acc[c], 8);
        acc[c] += __shfl_xor_sync(FULL, acc[c], 16);
    }

    if (grp == 0) {   // lanes 0-7: head = lane
        float inv = 1.0f / (den + 1e-16f);
        const float* bp = b1 + head * 8;
        float v[8];
        #pragma unroll
        for (int c = 0; c < 8; c++) {
            float t = acc[c] * inv + bp[c];
            v[c] = t > 0.0f ? t : expm1f(t);
        }
        float4* op = (float4*)(g_hx + (size_t)warp * HID + head * 8);
        op[0] = make_float4(v[0], v[1], v[2], v[3]);
        op[1] = make_float4(v[4], v[5], v[6], v[7]);
    }
}

// ================= GEMM 2: h2 = hx @ W2 (fp16 out) ; node alphas =============
__device__ __forceinline__ float f4elem(float4 v, int kk) {
    return kk == 0 ? v.x : kk == 1 ? v.y : kk == 2 ? v.z : v.w;
}
__device__ __forceinline__ ull pack2(float lo, float hi) {
    ull r; asm("mov.b64 %0,{%1,%2};" : "=l"(r) : "f"(lo), "f"(hi)); return r;
}
__device__ __forceinline__ void unpack2(ull v, float& lo, float& hi) {
    asm("mov.b64 {%0,%1},%2;" : "=f"(lo), "=f"(hi) : "l"(v));
}
__device__ __forceinline__ ull fma2(ull a, ull b, ull c) {
    ull d; asm("fma.rn.f32x2 %0,%1,%2,%3;" : "=l"(d) : "l"(a), "l"(b), "l"(c)); return d;
}
#define SX2_P4 17
__global__ __launch_bounds__(512) void gemm2_kernel(
    const float* __restrict__ W2,
    const float* __restrict__ as2, const float* __restrict__ ad2, int N)
{
    extern __shared__ float smem[];
    float*  sW  = smem;                        // 4096 floats
    float4* sXv = (float4*)(smem + HID * HID); // 256 rows x 17 float4

    int t = threadIdx.x;
    #pragma unroll
    for (int i = t; i < HID * HID / 4; i += 512)
        ((float4*)sW)[i] = ((const float4*)W2)[i];

    int nodeBase = blockIdx.x * 256;
    int rows = min(256, N - nodeBase);
    for (int i = t; i < rows * 16; i += 512) {
        int r = i >> 4, c = i & 15;
        sXv[r * SX2_P4 + c] = ((const float4*)(g_hx + (size_t)nodeBase * HID))[i];
    }
    __syncthreads();

    int j = t & 15;
    int g = t >> 4;

    ull acc[8][2];
    #pragma unroll
    for (int i = 0; i < 8; i++) { acc[i][0] = 0; acc[i][1] = 0; }

    #pragma unroll 4
    for (int k4 = 0; k4 < HID / 4; k4++) {
        float4 xv[8];
        #pragma unroll
        for (int i = 0; i < 8; i++) xv[i] = sXv[(g + 32 * i) * SX2_P4 + k4];
        #pragma unroll
        for (int kk = 0; kk < 4; kk++) {
            const ull* wr = (const ull*)(sW + (k4 * 4 + kk) * HID + j * 4);
            ull w0 = wr[0], w1 = wr[1];
            #pragma unroll
            for (int i = 0; i < 8; i++) {
                float xs = f4elem(xv[i], kk);
                ull xx = pack2(xs, xs);
                acc[i][0] = fma2(xx, w0, acc[i][0]);
                acc[i][1] = fma2(xx, w1, acc[i][1]);
            }
        }
    }

    #pragma unroll
    for (int i = 0; i < 8; i++) {
        int node = nodeBase + g + 32 * i;
        bool valid = node < N;
        float a[4];
        unpack2(acc[i][0], a[0], a[1]); unpack2(acc[i][1], a[2], a[3]);
        float s = 0.0f, d = 0.0f;
        #pragma unroll
        for (int c = 0; c < 4; c++) {
            s = fmaf(a[c], as2[j * 4 + c], s);
            d = fmaf(a[c], ad2[j * 4 + c], d);
        }
        #pragma unroll
        for (int o = 1; o < 16; o <<= 1) {
            s += __shfl_xor_sync(0xffffffffu, s, o);
            d += __shfl_xor_sync(0xffffffffu, d, o);
        }
        if (valid) {
            ((uint2*)(g_h2 + (size_t)node * HID))[j] = to_h4(a[0], a[1], a[2], a[3]);
            if (j == 0) { g_as2n[node] = s; g_ad2n[node] = d; }
        }
    }
}

// ================= layer-2 aggregation: shuffle-lean lane mapping ===========
// warp per dst node; lane = quarter*8 + q4; 4 edges in flight via uint4 rows.
__global__ __launch_bounds__(256) void agg2_kernel(const float* __restrict__ b2, int N)
{
    const unsigned FULL = 0xffffffffu;
    int warp = (blockIdx.x * blockDim.x + threadIdx.x) >> 5;
    int lane = threadIdx.x & 31;
    if (warp >= N) return;
    int beg = g_rowptr[warp], end = g_rowptr[warp + 1];

    int q4 = lane & 7;
    int quarter = lane >> 3;

    float adv = g_ad2n[warp];
    float acc[8] = {0,0,0,0,0,0,0,0};
    float den = 0.0f;

    for (int pb = beg; pb < end; pb += 32) {
        int p = pb + lane;
        bool v = p < end;
        int myidx = v ? g_col[p] : 0;
        float wl = v ? __expf(lrelu(g_as2n[myidx] + adv)) : 0.0f;
        den += wl;
        int cnt = min(32, end - pb);
        for (int k = 0; k < cnt; k += 4) {
            int el = k + quarter;                     // <= 31 always
            int s = __shfl_sync(FULL, myidx, el);
            float w = __shfl_sync(FULL, wl, el);      // 0 when el >= cnt (padded)
            uint4 u = *(const uint4*)(g_h2 + ((size_t)(unsigned)s << 6) + (q4 << 3));
            float2 f0 = __half22float2(*(__half2*)&u.x);
            float2 f1 = __half22float2(*(__half2*)&u.y);
            float2 f2 = __half22float2(*(__half2*)&u.z);
            float2 f3 = __half22float2(*(__half2*)&u.w);
            acc[0] = fmaf(w, f0.x, acc[0]); acc[1] = fmaf(w, f0.y, acc[1]);
            acc[2] = fmaf(w, f1.x, acc[2]); acc[3] = fmaf(w, f1.y, acc[3]);
            acc[4] = fmaf(w, f2.x, acc[4]); acc[5] = fmaf(w, f2.y, acc[5]);
            acc[6] = fmaf(w, f3.x, acc[6]); acc[7] = fmaf(w, f3.y, acc[7]);
        }
    }
    // den: full warp reduce; acc: reduce over quarters
    #pragma unroll
    for (int o = 1; o < 32; o <<= 1) den += __shfl_xor_sync(FULL, den, o);
    #pragma unroll
    for (int c = 0; c < 8; c++) {
        acc[c] += __shfl_xor_sync(FULL, acc[c], 8);
        acc[c] += __shfl_xor_sync(FULL, acc[c], 16);
    }

    if (quarter == 0) {   // lanes 0-7: q4 = lane
        float inv = 1.0f / (den + 1e-16f);
        const float* bp = b2 + q4 * 8;
        float v0 = acc[0] * inv + bp[0], v1 = acc[1] * inv + bp[1];
        float v2 = acc[2] * inv + bp[2], v3 = acc[3] * inv + bp[3];
        float v4 = acc[4] * inv + bp[4], v5 = acc[5] * inv + bp[5];
        float v6 = acc[6] * inv + bp[6], v7 = acc[7] * inv + bp[7];
        float4* op = (float4*)(g_z + (size_t)warp * HID + q4 * 8);
        op[0] = make_float4(v0, v1, v2, v3);
        op[1] = make_float4(v4, v5, v6, v7);
    }
}

// ================= decode + state reset =================
__global__ __launch_bounds__(256) void decode_kernel(
    const int* __restrict__ qe, float* __restrict__ out, int Q, int N)
{
    long long gid = (long long)blockIdx.x * blockDim.x + threadIdx.x;
    if (gid < N) g_cnt[(int)gid] = 0;
    if (gid < 128) g_state[(int)gid] = 0ull;
    int q = (int)(gid >> 3);
    int j = (int)(gid & 7);
    bool valid = q < Q;
    int qc = valid ? q : 0;
    int a = clampi(qe[qc], N);
    int b = clampi(qe[(size_t)Q + qc], N);
    const float4* za = (const float4*)(g_z + (size_t)a * HID + j * 8);
    const float4* zb = (const float4*)(g_z + (size_t)b * HID + j * 8);
    float4 a0 = za[0], a1 = za[1], b0 = zb[0], b1 = zb[1];
    float dot = a0.x * b0.x + a0.y * b0.y + a0.z * b0.z + a0.w * b0.w
              + a1.x * b1.x + a1.y * b1.y + a1.z * b1.z + a1.w * b1.w;
    #pragma unroll
    for (int o = 1; o < 8; o <<= 1) dot += __shfl_xor_sync(0xffffffffu, dot, o);
    if (valid && j == 0) out[q] = 1.0f / (1.0f + __expf(-dot));
}

// ================= launch =================
extern "C" void kernel_launch(void* const* d_in, const int* in_sizes, int n_in,
                              void* d_out, int out_size)
{
    const float* x   = (const float*)d_in[0];
    const int*   ei  = (const int*)d_in[1];
    const int*   qe  = (const int*)d_in[2];
    const float* W1  = (const float*)d_in[3];
    const float* as1 = (const float*)d_in[4];
    const float* ad1 = (const float*)d_in[5];
    const float* b1  = (const float*)d_in[6];
    const float* W2  = (const float*)d_in[7];
    const float* as2 = (const float*)d_in[8];
    const float* ad2 = (const float*)d_in[9];
    const float* b2  = (const float*)d_in[10];
    float*       out = (float*)d_out;

    int N = in_sizes[0] / DIM1;   // 100000
    int E = in_sizes[1] / 2;      // 1600000
    int Q = in_sizes[2] / 2;      // 100000
    int Etot = E + N;

    const int T = 256;
    int gE     = (E + T - 1) / T;
    int gGemm1 = (N + 127) / 128;
    int gGemm2 = (N + 255) / 256;
    int gWarp  = (N * 32 + T - 1) / T;
    int gDec   = (int)(((long long)Q * 8 + T - 1) / T);
    int nChunks = (N + 1023) / 1024;   // 98 <= 148 SMs: lookback-safe

    const int SMEM1 = (128 * SA_PITCH + 128 * SB_PITCH) * 2;   // 53,248 B
    const int SMEM2 = (HID * HID + 256 * SX2_P4 * 4) * 4;      // 86,016 B
    cudaFuncSetAttribute(gemm1_kernel, cudaFuncAttributeMaxDynamicSharedMemorySize, SMEM1);
    cudaFuncSetAttribute(gemm2_kernel, cudaFuncAttributeMaxDynamicSharedMemorySize, SMEM2);

    // single stream; agg1 is the 4th kernel launch (ncu capture slot)
    gemm1_kernel<<<gGemm1, T, SMEM1>>>(x, W1, as1, ad1, ei, E, N);  // + fused count
    scan_kernel<<<nChunks, 1024>>>(N, Etot);
    scatter_kernel<<<gE, T>>>(ei, E, N);
    agg1_kernel<<<gWarp, T>>>(b1, N);
    gemm2_kernel<<<gGemm2, 512, SMEM2>>>(W2, as2, ad2, N);
    agg2_kernel<<<gWarp, T>>>(b2, N);
    decode_kernel<<<gDec, T>>>(qe, out, Q, N);
}

// round 17
// speedup vs baseline: 1.1245x; 1.0388x over previous
#include <cuda_runtime.h>
#include <cuda_fp16.h>
#include <math.h>

#define NMAX 100000
#define EMAX 1700000
#define DIM1 128
#define HID  64

// ---------------- device scratch ----------------
__device__ __align__(16) __half g_h1[NMAX * HID];   // fp16 features (layer1)
__device__ __align__(16) __half g_h2[NMAX * HID];   // fp16 features (layer2)
__device__ __align__(16) float g_as1n[NMAX * 8];
__device__ __align__(16) float g_ad1n[NMAX * 8];
__device__ __align__(16) float g_hx  [NMAX * HID];
__device__ __align__(16) float g_as2n[NMAX];
__device__ __align__(16) float g_ad2n[NMAX];
__device__ __align__(16) float g_z   [NMAX * HID];
// CSR
__device__ int g_cnt   [NMAX];                       // counts -> cursors (reset by decode)
__device__ int g_rowptr[NMAX + 1];
__device__ int g_col   [EMAX];
__device__ unsigned long long g_state[128];          // lookback scan states (reset by decode)

// ---------------- helpers ----------------
__device__ __forceinline__ int clampi(int i, int N) {
    i = i < 0 ? 0 : i;
    return i >= N ? N - 1 : i;
}
__device__ __forceinline__ float lrelu(float v) { return v > 0.0f ? v : 0.2f * v; }

typedef unsigned long long ull;
__device__ __forceinline__ uint2 to_h4(float a0, float a1, float a2, float a3) {
    __half2 p0 = __float22half2_rn(make_float2(a0, a1));
    __half2 p1 = __float22half2_rn(make_float2(a2, a3));
    uint2 u;
    u.x = *(unsigned*)&p0;
    u.y = *(unsigned*)&p1;
    return u;
}
// tensor-core primitives
__device__ __forceinline__ void ldsm_x4(unsigned& r0, unsigned& r1, unsigned& r2, unsigned& r3, unsigned a) {
    asm volatile("ldmatrix.sync.aligned.m8n8.x4.shared.b16 {%0,%1,%2,%3}, [%4];"
                 : "=r"(r0), "=r"(r1), "=r"(r2), "=r"(r3) : "r"(a));
}
__device__ __forceinline__ void ldsm_x4t(unsigned& r0, unsigned& r1, unsigned& r2, unsigned& r3, unsigned a) {
    asm volatile("ldmatrix.sync.aligned.m8n8.x4.trans.shared.b16 {%0,%1,%2,%3}, [%4];"
                 : "=r"(r0), "=r"(r1), "=r"(r2), "=r"(r3) : "r"(a));
}
__device__ __forceinline__ void mma16816(float* c, unsigned a0, unsigned a1, unsigned a2, unsigned a3,
                                         unsigned b0, unsigned b1) {
    asm volatile("mma.sync.aligned.m16n8k16.row.col.f32.f16.f16.f32 "
                 "{%0,%1,%2,%3}, {%4,%5,%6,%7}, {%8,%9}, {%0,%1,%2,%3};"
                 : "+f"(c[0]), "+f"(c[1]), "+f"(c[2]), "+f"(c[3])
                 : "r"(a0), "r"(a1), "r"(a2), "r"(a3), "r"(b0), "r"(b1));
}

// ================= GEMM 1 (tensor cores) + fused edge count =================
#define SA_PITCH 136
#define SB_PITCH 72
__global__ __launch_bounds__(256) void gemm1_kernel(
    const float* __restrict__ x, const float* __restrict__ W1,
    const float* __restrict__ as1, const float* __restrict__ ad1,
    const int* __restrict__ ei, int E, int N)
{
    extern __shared__ __half smh[];
    __half* sA = smh;                     // 128 x 136 halves
    __half* sB = smh + 128 * SA_PITCH;    // 128 x 72 halves

    int t = threadIdx.x;

    // fused count: fire-and-forget atomics (grid-stride over dst indices)
    for (long long ii = (long long)blockIdx.x * 256 + t; ii < E; ii += (long long)gridDim.x * 256)
        atomicAdd(&g_cnt[clampi(ei[(size_t)E + ii], N)], 1);

    int nodeBase = blockIdx.x * 128;
    int rows = min(128, N - nodeBase);

    for (int i = t; i < 128 * 16; i += 256) {
        int r = i >> 4, c4 = i & 15;
        float4 v = ((const float4*)W1)[i];
        *(uint2*)&sB[r * SB_PITCH + c4 * 4] = to_h4(v.x, v.y, v.z, v.w);
    }
    for (int i = t; i < 128 * 32; i += 256) {
        int r = i >> 5, c4 = i & 31;
        float4 v = make_float4(0.f, 0.f, 0.f, 0.f);
        if (r < rows) v = ((const float4*)(x + (size_t)nodeBase * DIM1))[i];
        *(uint2*)&sA[r * SA_PITCH + c4 * 4] = to_h4(v.x, v.y, v.z, v.w);
    }
    __syncthreads();

    int w = t >> 5, lane = t & 31;
    unsigned sAc = (unsigned)__cvta_generic_to_shared(sA);
    unsigned sBc = (unsigned)__cvta_generic_to_shared(sB);
    unsigned aBase = sAc + ((16 * w + (lane & 15)) * SA_PITCH + (lane >> 4) * 8) * 2;
    unsigned bLane = sBc + ((lane & 15) * SB_PITCH + (lane >> 4) * 8) * 2;

    float acc[8][4];
    #pragma unroll
    for (int nt = 0; nt < 8; nt++)
        #pragma unroll
        for (int m = 0; m < 4; m++) acc[nt][m] = 0.0f;

    #pragma unroll
    for (int s = 0; s < 8; s++) {
        unsigned a0, a1, a2, a3;
        ldsm_x4(a0, a1, a2, a3, aBase + s * 32);
        unsigned bStep = bLane + s * 16 * SB_PITCH * 2;
        #pragma unroll
        for (int nt = 0; nt < 8; nt += 2) {
            unsigned b0, b1, b2, b3;
            ldsm_x4t(b0, b1, b2, b3, bStep + nt * 16);
            mma16816(acc[nt],     a0, a1, a2, a3, b0, b1);
            mma16816(acc[nt + 1], a0, a1, a2, a3, b2, b3);
        }
    }

    int r_lo = 16 * w + (lane >> 2);
    int node_lo = nodeBase + r_lo;
    int node_hi = node_lo + 8;
    int c2i = (lane & 3) * 2;
    bool vlo = node_lo < N, vhi = node_hi < N;

    #pragma unroll
    for (int tile = 0; tile < 8; tile++) {
        int col = tile * 8 + c2i;
        float a0v = acc[tile][0], a1v = acc[tile][1];
        float a2v = acc[tile][2], a3v = acc[tile][3];
        if (vlo) {
            __half2 hv = __float22half2_rn(make_float2(a0v, a1v));
            *(__half2*)&g_h1[(size_t)node_lo * HID + col] = hv;
        }
        if (vhi) {
            __half2 hv = __float22half2_rn(make_float2(a2v, a3v));
            *(__half2*)&g_h1[(size_t)node_hi * HID + col] = hv;
        }
        float s0 = as1[col], s1v = as1[col + 1];
        float d0 = ad1[col], d1v = ad1[col + 1];
        float sl = a0v * s0 + a1v * s1v, dl = a0v * d0 + a1v * d1v;
        float sh = a2v * s0 + a3v * s1v, dh = a2v * d0 + a3v * d1v;
        sl += __shfl_xor_sync(0xffffffffu, sl, 1); sl += __shfl_xor_sync(0xffffffffu, sl, 2);
        dl += __shfl_xor_sync(0xffffffffu, dl, 1); dl += __shfl_xor_sync(0xffffffffu, dl, 2);
        sh += __shfl_xor_sync(0xffffffffu, sh, 1); sh += __shfl_xor_sync(0xffffffffu, sh, 2);
        dh += __shfl_xor_sync(0xffffffffu, dh, 1); dh += __shfl_xor_sync(0xffffffffu, dh, 2);
        if ((lane & 3) == 0) {
            if (vlo) { g_as1n[node_lo * 8 + tile] = sl; g_ad1n[node_lo * 8 + tile] = dl; }
            if (vhi) { g_as1n[node_hi * 8 + tile] = sh; g_ad1n[node_hi * 8 + tile] = dh; }
        }
    }
}

// ================= single-pass scan (decoupled lookback) =====================
__global__ __launch_bounds__(1024) void scan_kernel(int N, int Etot) {
    __shared__ int warpsum[32];
    __shared__ int s_boff;
    const unsigned FULL = 0xffffffffu;
    int b = blockIdx.x, t = threadIdx.x;
    int lane = t & 31, wid = t >> 5;
    int i = b * 1024 + t;
    int v = (i < N) ? g_cnt[i] : 0;

    int xs = v;
    #pragma unroll
    for (int o = 1; o < 32; o <<= 1) {
        int y = __shfl_up_sync(FULL, xs, o);
        if (lane >= o) xs += y;
    }
    if (lane == 31) warpsum[wid] = xs;
    __syncthreads();
    if (wid == 0) {
        int s = warpsum[lane];
        #pragma unroll
        for (int o = 1; o < 32; o <<= 1) {
            int y = __shfl_up_sync(FULL, s, o);
            if (lane >= o) s += y;
        }
        warpsum[lane] = s;
    }
    __syncthreads();
    int incl = xs + (wid > 0 ? warpsum[wid - 1] : 0);
    int blocktot = warpsum[31];

    if (t == 0) {
        if (b == 0) {
            atomicExch(&g_state[0], ((ull)(unsigned)blocktot << 2) | 2ull);
            s_boff = 0;
        } else {
            atomicExch(&g_state[b], ((ull)(unsigned)blocktot << 2) | 1ull);
            int off = 0, p = b - 1;
            while (true) {
                ull s = atomicAdd(&g_state[p], 0ull);
                int st = (int)(s & 3ull);
                if (st == 0) continue;
                off += (int)(s >> 2);
                if (st == 2) break;
                p--;
            }
            atomicExch(&g_state[b], ((ull)(unsigned)(off + blocktot) << 2) | 2ull);
            s_boff = off;
        }
    }
    __syncthreads();
    int boff = s_boff;

    if (i < N) {
        int rp = (incl - v) + boff + i;   // exclusive scan + i self-loops before i
        g_rowptr[i] = rp;
        g_col[rp] = i;                    // self loop first in segment
        g_cnt[i] = rp + 1;                // scatter cursor
    }
    if (i == 0) g_rowptr[N] = Etot;
}

__global__ void scatter_kernel(const int* __restrict__ ei, int E, int N) {
    int i = blockIdx.x * blockDim.x + threadIdx.x;
    if (i >= E) return;
    int src = clampi(ei[i], N);
    int dst = clampi(ei[(size_t)E + i], N);
    int pos = atomicAdd(&g_cnt[dst], 1);
    g_col[pos] = src;
}

// ================= layer-1 aggregation: HFMA2 accumulation ==================
// warp per dst node. lane = grp*8 + head; head owns cols head*8..+7 (one uint4).
// Messages accumulate in half2 (HFMA2): 4 HFMA2 replace 8 cvt + 8 FFMA.
__global__ __launch_bounds__(256) void agg1_kernel(const float* __restrict__ b1, int N)
{
    const unsigned FULL = 0xffffffffu;
    int warp = (blockIdx.x * blockDim.x + threadIdx.x) >> 5;
    int lane = threadIdx.x & 31;
    if (warp >= N) return;
    int beg = g_rowptr[warp], end = g_rowptr[warp + 1];

    int head = lane & 7;
    int grp  = lane >> 3;

    float adv = g_ad1n[(size_t)warp * 8 + head];
    __half2 acc[4];
    acc[0] = __float2half2_rn(0.f); acc[1] = acc[0]; acc[2] = acc[0]; acc[3] = acc[0];
    float den = 0.0f;

    for (int pb = beg; pb < end; pb += 32) {
        int p = pb + lane;
        int myidx = (p < end) ? g_col[p] : 0;
        int cnt = min(32, end - pb);
        for (int k = 0; k < cnt; k += 4) {
            int eg = k + grp;
            int srcg = __shfl_sync(FULL, myidx, eg);   // eg <= 31 always
            float w = 0.0f;
            if (eg < cnt) {
                w = __expf(lrelu(g_as1n[srcg * 8 + head] + adv));
                den += w;
            }
            __half2 wh = __float2half2_rn(w);          // 0 beyond cnt -> no contribution
            uint4 u = *(const uint4*)(g_h1 + ((size_t)(unsigned)srcg << 6) + (head << 3));
            acc[0] = __hfma2(*(__half2*)&u.x, wh, acc[0]);
            acc[1] = __hfma2(*(__half2*)&u.y, wh, acc[1]);
            acc[2] = __hfma2(*(__half2*)&u.z, wh, acc[2]);
            acc[3] = __hfma2(*(__half2*)&u.w, wh, acc[3]);
        }
    }
    // reduce over the 4 edge groups (lanes head, head+8, head+16, head+24)
    den += __shfl_xor_sync(FULL, den, 8);
    den += __shfl_xor_sync(FULL, den, 16);
    #pragma unroll
    for (int c = 0; c < 4; c++) {
        unsigned uu = *(unsigned*)&acc[c];
        unsigned o8 = __shfl_xor_sync(FULL, uu, 8);
        acc[c] = __hadd2(acc[c], *(__half2*)&o8);
        uu = *(unsigned*)&acc[c];
        unsigned o16 = __shfl_xor_sync(FULL, uu, 16);
        acc[c] = __hadd2(acc[c], *(__half2*)&o16);
    }

    if (grp == 0) {   // lanes 0-7: head = lane
        float inv = 1.0f / (den + 1e-16f);
        const float* bp = b1 + head * 8;
        float v[8];
        #pragma unroll
        for (int c = 0; c < 4; c++) {
            float2 f = __half22float2(acc[c]);
            float t0 = f.x * inv + bp[2 * c];
            float t1 = f.y * inv + bp[2 * c + 1];
            v[2 * c]     = t0 > 0.0f ? t0 : expm1f(t0);
            v[2 * c + 1] = t1 > 0.0f ? t1 : expm1f(t1);
        }
        float4* op = (float4*)(g_hx + (size_t)warp * HID + head * 8);
        op[0] = make_float4(v[0], v[1], v[2], v[3]);
        op[1] = make_float4(v[4], v[5], v[6], v[7]);
    }
}

// ================= GEMM 2: h2 = hx @ W2 (fp16 out) ; node alphas =============
__device__ __forceinline__ float f4elem(float4 v, int kk) {
    return kk == 0 ? v.x : kk == 1 ? v.y : kk == 2 ? v.z : v.w;
}
__device__ __forceinline__ ull pack2(float lo, float hi) {
    ull r; asm("mov.b64 %0,{%1,%2};" : "=l"(r) : "f"(lo), "f"(hi)); return r;
}
__device__ __forceinline__ void unpack2(ull v, float& lo, float& hi) {
    asm("mov.b64 {%0,%1},%2;" : "=f"(lo), "=f"(hi) : "l"(v));
}
__device__ __forceinline__ ull fma2(ull a, ull b, ull c) {
    ull d; asm("fma.rn.f32x2 %0,%1,%2,%3;" : "=l"(d) : "l"(a), "l"(b), "l"(c)); return d;
}
#define SX2_P4 17
__global__ __launch_bounds__(512) void gemm2_kernel(
    const float* __restrict__ W2,
    const float* __restrict__ as2, const float* __restrict__ ad2, int N)
{
    extern __shared__ float smem[];
    float*  sW  = smem;                        // 4096 floats
    float4* sXv = (float4*)(smem + HID * HID); // 256 rows x 17 float4

    int t = threadIdx.x;
    #pragma unroll
    for (int i = t; i < HID * HID / 4; i += 512)
        ((float4*)sW)[i] = ((const float4*)W2)[i];

    int nodeBase = blockIdx.x * 256;
    int rows = min(256, N - nodeBase);
    for (int i = t; i < rows * 16; i += 512) {
        int r = i >> 4, c = i & 15;
        sXv[r * SX2_P4 + c] = ((const float4*)(g_hx + (size_t)nodeBase * HID))[i];
    }
    __syncthreads();

    int j = t & 15;
    int g = t >> 4;

    ull acc[8][2];
    #pragma unroll
    for (int i = 0; i < 8; i++) { acc[i][0] = 0; acc[i][1] = 0; }

    #pragma unroll 4
    for (int k4 = 0; k4 < HID / 4; k4++) {
        float4 xv[8];
        #pragma unroll
        for (int i = 0; i < 8; i++) xv[i] = sXv[(g + 32 * i) * SX2_P4 + k4];
        #pragma unroll
        for (int kk = 0; kk < 4; kk++) {
            const ull* wr = (const ull*)(sW + (k4 * 4 + kk) * HID + j * 4);
            ull w0 = wr[0], w1 = wr[1];
            #pragma unroll
            for (int i = 0; i < 8; i++) {
                float xs = f4elem(xv[i], kk);
                ull xx = pack2(xs, xs);
                acc[i][0] = fma2(xx, w0, acc[i][0]);
                acc[i][1] = fma2(xx, w1, acc[i][1]);
            }
        }
    }

    #pragma unroll
    for (int i = 0; i < 8; i++) {
        int node = nodeBase + g + 32 * i;
        bool valid = node < N;
        float a[4];
        unpack2(acc[i][0], a[0], a[1]); unpack2(acc[i][1], a[2], a[3]);
        float s = 0.0f, d = 0.0f;
        #pragma unroll
        for (int c = 0; c < 4; c++) {
            s = fmaf(a[c], as2[j * 4 + c], s);
            d = fmaf(a[c], ad2[j * 4 + c], d);
        }
        #pragma unroll
        for (int o = 1; o < 16; o <<= 1) {
            s += __shfl_xor_sync(0xffffffffu, s, o);
            d += __shfl_xor_sync(0xffffffffu, d, o);
        }
        if (valid) {
            ((uint2*)(g_h2 + (size_t)node * HID))[j] = to_h4(a[0], a[1], a[2], a[3]);
            if (j == 0) { g_as2n[node] = s; g_ad2n[node] = d; }
        }
    }
}

// ================= layer-2 aggregation: HFMA2 accumulation ==================
__global__ __launch_bounds__(256) void agg2_kernel(const float* __restrict__ b2, int N)
{
    const unsigned FULL = 0xffffffffu;
    int warp = (blockIdx.x * blockDim.x + threadIdx.x) >> 5;
    int lane = threadIdx.x & 31;
    if (warp >= N) return;
    int beg = g_rowptr[warp], end = g_rowptr[warp + 1];

    int q4 = lane & 7;
    int quarter = lane >> 3;

    float adv = g_ad2n[warp];
    __half2 acc[4];
    acc[0] = __float2half2_rn(0.f); acc[1] = acc[0]; acc[2] = acc[0]; acc[3] = acc[0];
    float den = 0.0f;

    for (int pb = beg; pb < end; pb += 32) {
        int p = pb + lane;
        bool v = p < end;
        int myidx = v ? g_col[p] : 0;
        float wl = v ? __expf(lrelu(g_as2n[myidx] + adv)) : 0.0f;
        den += wl;
        int cnt = min(32, end - pb);
        for (int k = 0; k < cnt; k += 4) {
            int el = k + quarter;                     // <= 31 always
            int s = __shfl_sync(FULL, myidx, el);
            float w = __shfl_sync(FULL, wl, el);      // 0 when el >= cnt (padded)
            __half2 wh = __float2half2_rn(w);
            uint4 u = *(const uint4*)(g_h2 + ((size_t)(unsigned)s << 6) + (q4 << 3));
            acc[0] = __hfma2(*(__half2*)&u.x, wh, acc[0]);
            acc[1] = __hfma2(*(__half2*)&u.y, wh, acc[1]);
            acc[2] = __hfma2(*(__half2*)&u.z, wh, acc[2]);
            acc[3] = __hfma2(*(__half2*)&u.w, wh, acc[3]);
        }
    }
    #pragma unroll
    for (int o = 1; o < 32; o <<= 1) den += __shfl_xor_sync(FULL, den, o);
    #pragma unroll
    for (int c = 0; c < 4; c++) {
        unsigned uu = *(unsigned*)&acc[c];
        unsigned o8 = __shfl_xor_sync(FULL, uu, 8);
        acc[c] = __hadd2(acc[c], *(__half2*)&o8);
        uu = *(unsigned*)&acc[c];
        unsigned o16 = __shfl_xor_sync(FULL, uu, 16);
        acc[c] = __hadd2(acc[c], *(__half2*)&o16);
    }

    if (quarter == 0) {   // lanes 0-7: q4 = lane
        float inv = 1.0f / (den + 1e-16f);
        const float* bp = b2 + q4 * 8;
        float v[8];
        #pragma unroll
        for (int c = 0; c < 4; c++) {
            float2 f = __half22float2(acc[c]);
            v[2 * c]     = f.x * inv + bp[2 * c];
            v[2 * c + 1] = f.y * inv + bp[2 * c + 1];
        }
        float4* op = (float4*)(g_z + (size_t)warp * HID + q4 * 8);
        op[0] = make_float4(v[0], v[1], v[2], v[3]);
        op[1] = make_float4(v[4], v[5], v[6], v[7]);
    }
}

// ================= decode + state reset =================
__global__ __launch_bounds__(256) void decode_kernel(
    const int* __restrict__ qe, float* __restrict__ out, int Q, int N)
{
    long long gid = (long long)blockIdx.x * blockDim.x + threadIdx.x;
    if (gid < N) g_cnt[(int)gid] = 0;
    if (gid < 128) g_state[(int)gid] = 0ull;
    int q = (int)(gid >> 3);
    int j = (int)(gid & 7);
    bool valid = q < Q;
    int qc = valid ? q : 0;
    int a = clampi(qe[qc], N);
    int b = clampi(qe[(size_t)Q + qc], N);
    const float4* za = (const float4*)(g_z + (size_t)a * HID + j * 8);
    const float4* zb = (const float4*)(g_z + (size_t)b * HID + j * 8);
    float4 a0 = za[0], a1 = za[1], b0 = zb[0], b1 = zb[1];
    float dot = a0.x * b0.x + a0.y * b0.y + a0.z * b0.z + a0.w * b0.w
              + a1.x * b1.x + a1.y * b1.y + a1.z * b1.z + a1.w * b1.w;
    #pragma unroll
    for (int o = 1; o < 8; o <<= 1) dot += __shfl_xor_sync(0xffffffffu, dot, o);
    if (valid && j == 0) out[q] = 1.0f / (1.0f + __expf(-dot));
}

// ================= launch =================
extern "C" void kernel_launch(void* const* d_in, const int* in_sizes, int n_in,
                              void* d_out, int out_size)
{
    const float* x   = (const float*)d_in[0];
    const int*   ei  = (const int*)d_in[1];
    const int*   qe  = (const int*)d_in[2];
    const float* W1  = (const float*)d_in[3];
    const float* as1 = (const float*)d_in[4];
    const float* ad1 = (const float*)d_in[5];
    const float* b1  = (const float*)d_in[6];
    const float* W2  = (const float*)d_in[7];
    const float* as2 = (const float*)d_in[8];
    const float* ad2 = (const float*)d_in[9];
    const float* b2  = (const float*)d_in[10];
    float*       out = (float*)d_out;

    int N = in_sizes[0] / DIM1;   // 100000
    int E = in_sizes[1] / 2;      // 1600000
    int Q = in_sizes[2] / 2;      // 100000
    int Etot = E + N;

    const int T = 256;
    int gE     = (E + T - 1) / T;
    int gGemm1 = (N + 127) / 128;
    int gGemm2 = (N + 255) / 256;
    int gWarp  = (N * 32 + T - 1) / T;
    int gDec   = (int)(((long long)Q * 8 + T - 1) / T);
    int nChunks = (N + 1023) / 1024;   // 98 <= 148 SMs: lookback-safe

    const int SMEM1 = (128 * SA_PITCH + 128 * SB_PITCH) * 2;   // 53,248 B
    const int SMEM2 = (HID * HID + 256 * SX2_P4 * 4) * 4;      // 86,016 B
    cudaFuncSetAttribute(gemm1_kernel, cudaFuncAttributeMaxDynamicSharedMemorySize, SMEM1);
    cudaFuncSetAttribute(gemm2_kernel, cudaFuncAttributeMaxDynamicSharedMemorySize, SMEM2);

    // single stream; agg1 is the 4th kernel launch (ncu capture slot)
    gemm1_kernel<<<gGemm1, T, SMEM1>>>(x, W1, as1, ad1, ei, E, N);  // + fused count
    scan_kernel<<<nChunks, 1024>>>(N, Etot);
    scatter_kernel<<<gE, T>>>(ei, E, N);
    agg1_kernel<<<gWarp, T>>>(b1, N);
    gemm2_kernel<<<gGemm2, 512, SMEM2>>>(W2, as2, ad2, N);
    agg2_kernel<<<gWarp, T>>>(b2, N);
    decode_kernel<<<gDec, T>>>(qe, out, Q, N);
}